// round 16
// baseline (speedup 1.0000x reference)
#include <cuda_runtime.h>
#include <cuda_bf16.h>
#include <math.h>
#include <stdint.h>

// Problem constants
#define Hd   256      // hidden
#define Ed   128      // embedding
#define Bd   32       // batch
#define Sd   128      // src len
#define Td   64       // trg len
#define Vd   32000    // vocab
#define G4   1024     // 4*H

#define NBLK 128
#define NTHR 256
#define NSTEPS (Sd + Td - 1)   // 191

#define MPAD 2048     // padded M for FC (2016 -> 2048)
#define FMROWS ((Td - 1) * Bd)   // 2016

// ---------------- device scratch (static, no runtime alloc) ----------------
__device__ float g_h0[Hd * Bd];
__device__ float g_h1[Hd * Bd];
__device__ float g_xe[Sd * G4 * Bd];
__device__ float g_xd[(Td - 1) * G4 * Bd];
__device__ unsigned g_bar8[8 * 64];             // 8 barrier counters, 256B apart

// bf16 split operands for the FC GEMM
__device__ __nv_bfloat16 g_Whi[Vd * Hd];
__device__ __nv_bfloat16 g_Wlo[Vd * Hd];
__device__ __nv_bfloat16 g_Ahi[MPAD * Hd];
__device__ __nv_bfloat16 g_Alo[MPAD * Hd];

__device__ __forceinline__ float sigm(float x) { return 1.0f / (1.0f + __expf(-x)); }

__device__ __forceinline__ float2 ffma2(float2 a, float2 b, float2 c) {
    unsigned long long au, bu, cu, du;
    au = *reinterpret_cast<unsigned long long*>(&a);
    bu = *reinterpret_cast<unsigned long long*>(&b);
    cu = *reinterpret_cast<unsigned long long*>(&c);
    asm("fma.rn.f32x2 %0, %1, %2, %3;" : "=l"(du) : "l"(au), "l"(bu), "l"(cu));
    return *reinterpret_cast<float2*>(&du);
}

__device__ __forceinline__ unsigned ld_relaxed(const unsigned* p) {
    unsigned v;
    asm volatile("ld.relaxed.gpu.u32 %0, [%1];" : "=r"(v) : "l"(p));
    return v;
}

__device__ __forceinline__ uint32_t smem_u32(const void* p) {
    uint32_t a;
    asm("{ .reg .u64 t; cvta.to.shared.u64 t, %1; cvt.u32.u64 %0, t; }" : "=r"(a) : "l"(p));
    return a;
}

// ---------------- init ----------------
__global__ void init_kernel(float* __restrict__ out) {
    int idx = blockIdx.x * blockDim.x + threadIdx.x;
    int stride = gridDim.x * blockDim.x;
    const int total = Bd * Vd;
    for (int i = idx; i < total; i += stride) {
        int b = i / Vd, v = i - b * Vd;
        out[(size_t)b * Td * Vd + v] = 0.0f;
    }
    if (idx < Hd * Bd) { g_h0[idx] = 0.0f; g_h1[idx] = 0.0f; }
    // zero-pad A rows [2016, 2048)
    if (idx < (MPAD - FMROWS) * Hd) {
        g_Ahi[(size_t)FMROWS * Hd + idx] = __float2bfloat16(0.0f);
        g_Alo[(size_t)FMROWS * Hd + idx] = __float2bfloat16(0.0f);
    }
    if (idx < 8 * 64) g_bar8[idx] = 0u;
}

// ---------------- input projection ----------------
// grid (8, T): block gathers x once, then loops over 4 subtiles of 32 rows.
__global__ void proj_kernel(const int* __restrict__ tok, int tok_stride,
                            const float* __restrict__ emb,
                            const float* __restrict__ Wih,
                            const float* __restrict__ bias,
                            int which) {
    __shared__ float x_s[Ed * Bd];   // [e][b] 16KB
    __shared__ float w_s[32 * Ed];   // [rlocal][e] 16KB
    float* xproj = which ? g_xd : g_xe;

    int t = blockIdx.y;
    int tid = threadIdx.x;

    for (int idx = tid; idx < Bd * Ed; idx += 256) {
        int b = idx >> 7, e = idx & 127;
        x_s[e * Bd + b] = emb[(size_t)tok[b * tok_stride + t] * Ed + e];
    }

    const int lane = tid & 31;
    const int wr = tid >> 5;

#pragma unroll
    for (int st = 0; st < 4; st++) {
        const int rbase = (blockIdx.x * 4 + st) * 32;
        __syncthreads();   // x ready (st=0) / previous compute done (st>0)
        for (int idx = tid; idx < 32 * Ed; idx += 256)
            w_s[idx] = Wih[(size_t)rbase * Ed + idx];
        __syncthreads();

        float acc[4];
#pragma unroll
        for (int i = 0; i < 4; i++) acc[i] = bias[rbase + wr * 4 + i];

#pragma unroll 4
        for (int k = 0; k < Ed; k++) {
            float xv = x_s[k * Bd + lane];
#pragma unroll
            for (int i = 0; i < 4; i++)
                acc[i] = fmaf(w_s[(wr * 4 + i) * Ed + k], xv, acc[i]);
        }

        float* o = xproj + ((size_t)t * G4 + rbase + wr * 4) * Bd + lane;
#pragma unroll
        for (int i = 0; i < 4; i++) o[(size_t)i * Bd] = acc[i];
    }
}

// ---------------- persistent recurrence kernel (R14 core; 8-way split barrier) ----------------
__global__ void __launch_bounds__(NTHR, 1) recur_kernel(
    const float* __restrict__ Whh_e,
    const float* __restrict__ Whh_d,
    float* __restrict__ out)
{
    __shared__ float  w_s[8 * Hd];        // [r][k] 8KB
    __shared__ float2 part[8][8][16];     // [warp][r][bp] 8KB
    __shared__ float2 g_sm[8][16];        // reduced gates [r][bp]
    __shared__ float2 c_sm[32];           // c state

    const int tid  = threadIdx.x;
    const int u0   = blockIdx.x * 2;
    const int lane = tid & 31;
    const int w    = tid >> 5;
    const int bp   = lane & 15;
    const int ksub = lane >> 4;
    const int kb   = w * 32 + ksub * 16;  // this thread's k base (16 ks)

    for (int i = tid; i < 8 * Hd; i += NTHR) {
        int r = i >> 8, k = i & 255;
        w_s[i] = Whh_e[(size_t)((r & 3) * Hd + u0 + (r >> 2)) * Hd + k];
    }
    if (tid < 32) c_sm[tid] = make_float2(0.f, 0.f);
    __syncthreads();

    const int rr = tid >> 4, bq = tid & 15;
    const int growr = (rr & 3) * Hd + u0 + (rr >> 2);

    float2 xcur = make_float2(0.f, 0.f);
    if (tid < 128)
        xcur = *(const float2*)(g_xe + (size_t)growr * Bd + bq * 2);

    for (int step = 0; step < NSTEPS; step++) {
        const bool dec = (step >= Sd);
        const int  t   = dec ? step - Sd : step;

        if (step == Sd) {
            for (int i = tid; i < 8 * Hd; i += NTHR) {
                int r = i >> 8, k = i & 255;
                w_s[i] = Whh_d[(size_t)((r & 3) * Hd + u0 + (r >> 2)) * Hd + k];
            }
            __syncthreads();
        }

        const float2* hp = (const float2*)((step & 1) ? g_h0 : g_h1);

        float2 hv[16];
#pragma unroll
        for (int j = 0; j < 16; j++)
            hv[j] = hp[(kb + j) * 16 + bp];

        float2 acc[8];
#pragma unroll
        for (int r = 0; r < 8; r++) acc[r] = make_float2(0.f, 0.f);
#pragma unroll
        for (int j = 0; j < 16; j += 4) {
#pragma unroll
            for (int r = 0; r < 8; r++) {
                float4 wv = *(const float4*)(w_s + r * Hd + kb + j);
                acc[r] = ffma2(make_float2(wv.x, wv.x), hv[j + 0], acc[r]);
                acc[r] = ffma2(make_float2(wv.y, wv.y), hv[j + 1], acc[r]);
                acc[r] = ffma2(make_float2(wv.z, wv.z), hv[j + 2], acc[r]);
                acc[r] = ffma2(make_float2(wv.w, wv.w), hv[j + 3], acc[r]);
            }
        }
#pragma unroll
        for (int r = 0; r < 8; r++) {
            acc[r].x += __shfl_xor_sync(0xffffffff, acc[r].x, 16);
            acc[r].y += __shfl_xor_sync(0xffffffff, acc[r].y, 16);
        }
        if (ksub == 0) {
#pragma unroll
            for (int r = 0; r < 8; r++) part[w][r][bp] = acc[r];
        }
        __syncthreads();

        if (tid < 128) {
            float2 s = xcur;
#pragma unroll
            for (int ww = 0; ww < 8; ww++) {
                float2 p = part[ww][rr][bq];
                s.x += p.x; s.y += p.y;
            }
            g_sm[rr][bq] = s;
            if (step + 1 < NSTEPS) {
                const bool decn = (step + 1 >= Sd);
                const int  tn   = decn ? step + 1 - Sd : step + 1;
                const float* xp = decn ? g_xd : g_xe;
                xcur = *(const float2*)(xp + ((size_t)tn * G4 + growr) * Bd + bq * 2);
            }
        }
        __syncthreads();

        float* hw = (step & 1) ? g_h1 : g_h0;
        if (tid < 32) {
            int iu2 = tid >> 4, bp2 = tid & 15;
            float2 gi = g_sm[iu2 * 4 + 0][bp2];
            float2 gf = g_sm[iu2 * 4 + 1][bp2];
            float2 gg = g_sm[iu2 * 4 + 2][bp2];
            float2 go = g_sm[iu2 * 4 + 3][bp2];
            float2 c = c_sm[tid];
            c.x = sigm(gf.x) * c.x + sigm(gi.x) * tanhf(gg.x);
            c.y = sigm(gf.y) * c.y + sigm(gi.y) * tanhf(gg.y);
            float2 h;
            h.x = sigm(go.x) * tanhf(c.x);
            h.y = sigm(go.y) * tanhf(c.y);
            c_sm[tid] = c;
            int u = u0 + iu2;
            *(float2*)(hw + u * Bd + bp2 * 2) = h;
            if (dec) {
                int m0 = t * Bd + bp2 * 2;
                __nv_bfloat16 xh = __float2bfloat16(h.x);
                __nv_bfloat16 xl = __float2bfloat16(h.x - __bfloat162float(xh));
                __nv_bfloat16 yh = __float2bfloat16(h.y);
                __nv_bfloat16 yl = __float2bfloat16(h.y - __bfloat162float(yh));
                g_Ahi[(size_t)m0 * Hd + u]       = xh;
                g_Alo[(size_t)m0 * Hd + u]       = xl;
                g_Ahi[(size_t)(m0 + 1) * Hd + u] = yh;
                g_Alo[(size_t)(m0 + 1) * Hd + u] = yl;
            }
            if (step == NSTEPS - 1) {
                size_t base = (size_t)Bd * Td * Vd;
                int b0 = bp2 * 2;
                out[base + (size_t)b0 * Hd + u]       = h.x;
                out[base + (size_t)(b0 + 1) * Hd + u] = h.y;
                out[base + (size_t)Bd * Hd + (size_t)b0 * Hd + u]       = c.x;
                out[base + (size_t)Bd * Hd + (size_t)(b0 + 1) * Hd + u] = c.y;
            }
        }
        __syncthreads();   // h stores complete block-wide

        // grid barrier: 8 split counters (256B apart), MLP-8 poll, one acquire fence
        if (step < NSTEPS - 1) {
            if (tid == 0) {
                __threadfence();
                atomicAdd(&g_bar8[(blockIdx.x & 7) << 6], 1u);
                const unsigned target = (unsigned)(16 * (step + 1));
                for (;;) {
                    unsigned c0 = ld_relaxed(&g_bar8[0 << 6]);
                    unsigned c1 = ld_relaxed(&g_bar8[1 << 6]);
                    unsigned c2 = ld_relaxed(&g_bar8[2 << 6]);
                    unsigned c3 = ld_relaxed(&g_bar8[3 << 6]);
                    unsigned c4 = ld_relaxed(&g_bar8[4 << 6]);
                    unsigned c5 = ld_relaxed(&g_bar8[5 << 6]);
                    unsigned c6 = ld_relaxed(&g_bar8[6 << 6]);
                    unsigned c7 = ld_relaxed(&g_bar8[7 << 6]);
                    unsigned m01 = min(c0, c1), m23 = min(c2, c3);
                    unsigned m45 = min(c4, c5), m67 = min(c6, c7);
                    if (min(min(m01, m23), min(m45, m67)) >= target) break;
                }
                asm volatile("fence.acq_rel.gpu;" ::: "memory");
            }
            __syncthreads();
        }
    }
}

// ---------------- bf16 split conversion for W ----------------
__global__ void convW_kernel(const float* __restrict__ W) {
    int i = blockIdx.x * blockDim.x + threadIdx.x;   // group of 4 floats
    const int total = Vd * Hd / 4;
    if (i >= total) return;
    float4 v = ((const float4*)W)[i];
    __nv_bfloat162 h01, h23, l01, l23;
    h01.x = __float2bfloat16(v.x); l01.x = __float2bfloat16(v.x - __bfloat162float(h01.x));
    h01.y = __float2bfloat16(v.y); l01.y = __float2bfloat16(v.y - __bfloat162float(h01.y));
    h23.x = __float2bfloat16(v.z); l23.x = __float2bfloat16(v.z - __bfloat162float(h23.x));
    h23.y = __float2bfloat16(v.w); l23.y = __float2bfloat16(v.w - __bfloat162float(h23.y));
    ((__nv_bfloat162*)g_Whi)[i * 2]     = h01;
    ((__nv_bfloat162*)g_Whi)[i * 2 + 1] = h23;
    ((__nv_bfloat162*)g_Wlo)[i * 2]     = l01;
    ((__nv_bfloat162*)g_Wlo)[i * 2 + 1] = l23;
}

// ---------------- FC via mma.sync (bf16 split, HMMA, cp.async double-buffer) ----------------
#define BKC   32
#define NCH   (Hd / BKC)      // 8
#define LDA   40              // smem row stride (bf16) — conflict-free for ldmatrix
#define TILE_BYTES (128 * LDA * 2)   // 10240 per tile
#define STG_SZ (4 * TILE_BYTES)      // 40960 per stage (AH, AL, BH, BL)
#define SM_BIAS (2 * STG_SZ)         // 81920
#define SM_TOTAL (SM_BIAS + 512)     // 82432

__device__ __forceinline__ void cp16(uint32_t dst, const void* src) {
    asm volatile("cp.async.cg.shared.global [%0], [%1], 16;" :: "r"(dst), "l"(src));
}
#define CP_COMMIT() asm volatile("cp.async.commit_group;" ::: "memory")

__device__ __forceinline__ void ldsm_x4(uint32_t* r, uint32_t addr) {
    asm volatile("ldmatrix.sync.aligned.m8n8.x4.shared.b16 {%0,%1,%2,%3}, [%4];"
                 : "=r"(r[0]), "=r"(r[1]), "=r"(r[2]), "=r"(r[3]) : "r"(addr));
}
__device__ __forceinline__ void ldsm_x2(uint32_t* r, uint32_t addr) {
    asm volatile("ldmatrix.sync.aligned.m8n8.x2.shared.b16 {%0,%1}, [%2];"
                 : "=r"(r[0]), "=r"(r[1]) : "r"(addr));
}
__device__ __forceinline__ void mma16816(float* c, const uint32_t* a, const uint32_t* b) {
    asm volatile("mma.sync.aligned.m16n8k16.row.col.f32.bf16.bf16.f32 "
                 "{%0,%1,%2,%3}, {%4,%5,%6,%7}, {%8,%9}, {%0,%1,%2,%3};"
                 : "+f"(c[0]), "+f"(c[1]), "+f"(c[2]), "+f"(c[3])
                 : "r"(a[0]), "r"(a[1]), "r"(a[2]), "r"(a[3]), "r"(b[0]), "r"(b[1]));
}

__global__ void __launch_bounds__(256) fcmma_kernel(const float* __restrict__ bias,
                                                    float* __restrict__ out)
{
    extern __shared__ __align__(16) char dsm[];

    const int tid = threadIdx.x;
    const int lane = tid & 31;
    const int wid = tid >> 5;
    const int vbase = blockIdx.x * 128;
    const int mbase = blockIdx.y * 128;
    const int warp_m = (wid & 1) * 64;
    const int warp_n = (wid >> 1) * 32;

    float* bias_s = (float*)(dsm + SM_BIAS);
    if (tid < 32) ((float4*)bias_s)[tid] = ((const float4*)(bias + vbase))[tid];

    const uint32_t sb = smem_u32(dsm);

    // copy-thread mapping: idx in [0,512) covers 128 rows x 4 16B-chunks
    const int cr0 = tid >> 2,          cj0 = (tid & 3);
    const int cr1 = (tid + 256) >> 2,  cj1 = ((tid + 256) & 3);

    auto issue = [&](int ch, int stg) {
        const int kk = ch * BKC;
        const uint32_t base = sb + stg * STG_SZ;
        {
            uint32_t d = base + (uint32_t)(cr0 * LDA + cj0 * 8) * 2;
            const size_t ga = (size_t)(mbase + cr0) * Hd + kk + cj0 * 8;
            const size_t gb = (size_t)(vbase + cr0) * Hd + kk + cj0 * 8;
            cp16(d,                  g_Ahi + ga);
            cp16(d + TILE_BYTES,     g_Alo + ga);
            cp16(d + 2 * TILE_BYTES, g_Whi + gb);
            cp16(d + 3 * TILE_BYTES, g_Wlo + gb);
        }
        {
            uint32_t d = base + (uint32_t)(cr1 * LDA + cj1 * 8) * 2;
            const size_t ga = (size_t)(mbase + cr1) * Hd + kk + cj1 * 8;
            const size_t gb = (size_t)(vbase + cr1) * Hd + kk + cj1 * 8;
            cp16(d,                  g_Ahi + ga);
            cp16(d + TILE_BYTES,     g_Alo + ga);
            cp16(d + 2 * TILE_BYTES, g_Whi + gb);
            cp16(d + 3 * TILE_BYTES, g_Wlo + gb);
        }
    };

    const int arow = warp_m + (lane & 15);
    const int acol = (lane >> 4) << 3;
    const int l16  = lane & 15;
    const int brow = warp_n + (l16 & 7);
    const int bcol = ((l16 >> 3) & 1) << 3;

    float acc[4][4][4];
#pragma unroll
    for (int i = 0; i < 4; i++)
#pragma unroll
        for (int j = 0; j < 4; j++)
#pragma unroll
            for (int r = 0; r < 4; r++) acc[i][j][r] = 0.0f;

    issue(0, 0);
    CP_COMMIT();

    for (int ch = 0; ch < NCH; ch++) {
        if (ch + 1 < NCH) {
            issue(ch + 1, (ch + 1) & 1);
            CP_COMMIT();
            asm volatile("cp.async.wait_group 1;" ::: "memory");
        } else {
            asm volatile("cp.async.wait_group 0;" ::: "memory");
        }
        __syncthreads();

        const uint32_t stg = sb + (ch & 1) * STG_SZ;
        const uint32_t uAh = stg;
        const uint32_t uAl = stg + TILE_BYTES;
        const uint32_t uBh = stg + 2 * TILE_BYTES;
        const uint32_t uBl = stg + 3 * TILE_BYTES;

#pragma unroll
        for (int k16 = 0; k16 < BKC; k16 += 16) {
            uint32_t bh[4][2], bl[4][2];
#pragma unroll
            for (int ni = 0; ni < 4; ni++) {
                uint32_t boff = (uint32_t)(((brow + ni * 8) * LDA + k16 + bcol) * 2);
                ldsm_x2(bh[ni], uBh + boff);
                ldsm_x2(bl[ni], uBl + boff);
            }
#pragma unroll
            for (int mi = 0; mi < 4; mi++) {
                uint32_t aoff = (uint32_t)(((arow + mi * 16) * LDA + k16 + acol) * 2);
                uint32_t ah[4], al[4];
                ldsm_x4(ah, uAh + aoff);
                ldsm_x4(al, uAl + aoff);
#pragma unroll
                for (int ni = 0; ni < 4; ni++) {
                    mma16816(acc[mi][ni], ah, bh[ni]);
                    mma16816(acc[mi][ni], ah, bl[ni]);
                    mma16816(acc[mi][ni], al, bh[ni]);
                }
            }
        }
        __syncthreads();
    }

    // epilogue: direct gmem writes with bias
#pragma unroll
    for (int mi = 0; mi < 4; mi++) {
        int gm0 = mbase + warp_m + mi * 16 + (lane >> 2);
#pragma unroll
        for (int ni = 0; ni < 4; ni++) {
            int cloc = warp_n + ni * 8 + ((lane & 3) << 1);
            int gv = vbase + cloc;
            float b0 = bias_s[cloc], b1 = bias_s[cloc + 1];
#pragma unroll
            for (int half = 0; half < 2; half++) {
                int gm = gm0 + half * 8;
                if (gm < FMROWS) {
                    int b = gm & 31, t = gm >> 5;
                    float2 r;
                    r.x = acc[mi][ni][half * 2 + 0] + b0;
                    r.y = acc[mi][ni][half * 2 + 1] + b1;
                    *(float2*)(out + ((size_t)b * Td + t + 1) * Vd + gv) = r;
                }
            }
        }
    }
}

// ---------------- launch (fork-join stream overlap, graph-capturable) ----------------
extern "C" void kernel_launch(void* const* d_in, const int* in_sizes, int n_in,
                              void* d_out, int out_size)
{
    const int*   src     = (const int*)  d_in[0];
    const int*   trg     = (const int*)  d_in[1];
    const float* emb_src = (const float*)d_in[2];
    const float* Wih_e   = (const float*)d_in[3];
    const float* Whh_e   = (const float*)d_in[4];
    const float* b_e     = (const float*)d_in[5];
    const float* emb_trg = (const float*)d_in[6];
    const float* Wih_d   = (const float*)d_in[7];
    const float* Whh_d   = (const float*)d_in[8];
    const float* b_d     = (const float*)d_in[9];
    const float* Wfc     = (const float*)d_in[10];
    const float* bfc     = (const float*)d_in[11];
    float* out = (float*)d_out;

    // Static side streams/events (created once, outside any capture)
    static cudaStream_t sB = nullptr, sC = nullptr;
    static cudaEvent_t eRoot = nullptr, eB = nullptr, eC = nullptr;
    if (sB == nullptr) {
        cudaStreamCreateWithFlags(&sB, cudaStreamNonBlocking);
        cudaStreamCreateWithFlags(&sC, cudaStreamNonBlocking);
        cudaEventCreateWithFlags(&eRoot, cudaEventDisableTiming);
        cudaEventCreateWithFlags(&eB, cudaEventDisableTiming);
        cudaEventCreateWithFlags(&eC, cudaEventDisableTiming);
        cudaFuncSetAttribute(fcmma_kernel,
                             cudaFuncAttributeMaxDynamicSharedMemorySize, SM_TOTAL);
    }

    // fork from the (captured) default stream
    cudaEventRecord(eRoot, 0);
    cudaStreamWaitEvent(sB, eRoot, 0);
    cudaStreamWaitEvent(sC, eRoot, 0);

    // branch B: init + decoder projection (needed by recur)
    init_kernel<<<512, 256, 0, sB>>>(out);
    proj_kernel<<<dim3(8, Td - 1), 256, 0, sB>>>(trg, Td, emb_trg, Wih_d, b_d, 1);
    cudaEventRecord(eB, sB);

    // branch C: FC weight split (needed only by fcmma)
    convW_kernel<<<(Vd * Hd / 4 + 255) / 256, 256, 0, sC>>>(Wfc);
    cudaEventRecord(eC, sC);

    // main stream: encoder projection, then recurrence, then FC
    proj_kernel<<<dim3(8, Sd), 256>>>(src, Sd, emb_src, Wih_e, b_e, 0);

    cudaStreamWaitEvent(0, eB, 0);   // init + proj_dec done
    recur_kernel<<<NBLK, NTHR>>>(Whh_e, Whh_d, out);

    cudaStreamWaitEvent(0, eC, 0);   // convW done
    fcmma_kernel<<<dim3(Vd / 128, MPAD / 128), 256, SM_TOTAL>>>(bfc, out);
}

// round 17
// speedup vs baseline: 1.0628x; 1.0628x over previous
#include <cuda_runtime.h>
#include <cuda_bf16.h>
#include <math.h>
#include <stdint.h>

// Problem constants
#define Hd   256      // hidden
#define Ed   128      // embedding
#define Bd   32       // batch
#define Sd   128      // src len
#define Td   64       // trg len
#define Vd   32000    // vocab
#define G4   1024     // 4*H

#define NBLK 128
#define NTHR 256
#define NSTEPS (Sd + Td - 1)   // 191

#define MPAD 2048     // padded M for FC (2016 -> 2048)
#define FMROWS ((Td - 1) * Bd)   // 2016

// ---------------- device scratch (static, no runtime alloc) ----------------
__device__ float g_h0[Hd * Bd];
__device__ float g_h1[Hd * Bd];
__device__ float g_xe[Sd * G4 * Bd];
__device__ float g_xd[(Td - 1) * G4 * Bd];
__device__ unsigned g_bar;                      // global barrier counter

// bf16 split operands for the FC GEMM
__device__ __nv_bfloat16 g_Whi[Vd * Hd];
__device__ __nv_bfloat16 g_Wlo[Vd * Hd];
__device__ __nv_bfloat16 g_Ahi[MPAD * Hd];
__device__ __nv_bfloat16 g_Alo[MPAD * Hd];

__device__ __forceinline__ float sigm(float x) { return 1.0f / (1.0f + __expf(-x)); }

__device__ __forceinline__ float2 ffma2(float2 a, float2 b, float2 c) {
    unsigned long long au, bu, cu, du;
    au = *reinterpret_cast<unsigned long long*>(&a);
    bu = *reinterpret_cast<unsigned long long*>(&b);
    cu = *reinterpret_cast<unsigned long long*>(&c);
    asm("fma.rn.f32x2 %0, %1, %2, %3;" : "=l"(du) : "l"(au), "l"(bu), "l"(cu));
    return *reinterpret_cast<float2*>(&du);
}

__device__ __forceinline__ unsigned ld_acquire_gpu(unsigned* p) {
    unsigned v;
    asm volatile("ld.acquire.gpu.u32 %0, [%1];" : "=r"(v) : "l"(p));
    return v;
}

__device__ __forceinline__ uint32_t smem_u32(const void* p) {
    uint32_t a;
    asm("{ .reg .u64 t; cvta.to.shared.u64 t, %1; cvt.u32.u64 %0, t; }" : "=r"(a) : "l"(p));
    return a;
}

// ---------------- init ----------------
__global__ void init_kernel(float* __restrict__ out) {
    int idx = blockIdx.x * blockDim.x + threadIdx.x;
    int stride = gridDim.x * blockDim.x;
    const int total = Bd * Vd;
    for (int i = idx; i < total; i += stride) {
        int b = i / Vd, v = i - b * Vd;
        out[(size_t)b * Td * Vd + v] = 0.0f;
    }
    if (idx < Hd * Bd) { g_h0[idx] = 0.0f; g_h1[idx] = 0.0f; }
    // zero-pad A rows [2016, 2048)
    if (idx < (MPAD - FMROWS) * Hd) {
        g_Ahi[(size_t)FMROWS * Hd + idx] = __float2bfloat16(0.0f);
        g_Alo[(size_t)FMROWS * Hd + idx] = __float2bfloat16(0.0f);
    }
    if (idx == 0) g_bar = 0u;
}

// ---------------- input projection ----------------
// grid (4, T): block gathers x once, then loops over 8 subtiles of 32 rows.
__global__ void proj_kernel(const int* __restrict__ tok, int tok_stride,
                            const float* __restrict__ emb,
                            const float* __restrict__ Wih,
                            const float* __restrict__ bias,
                            int which) {
    __shared__ float x_s[Ed * Bd];   // [e][b] 16KB
    __shared__ float w_s[32 * Ed];   // [rlocal][e] 16KB
    float* xproj = which ? g_xd : g_xe;

    int t = blockIdx.y;
    int tid = threadIdx.x;

    for (int idx = tid; idx < Bd * Ed; idx += 256) {
        int b = idx >> 7, e = idx & 127;
        x_s[e * Bd + b] = emb[(size_t)tok[b * tok_stride + t] * Ed + e];
    }

    const int lane = tid & 31;
    const int wr = tid >> 5;

#pragma unroll
    for (int st = 0; st < 8; st++) {
        const int rbase = (blockIdx.x * 8 + st) * 32;
        __syncthreads();   // x ready (st=0) / previous compute done (st>0)
        for (int idx = tid; idx < 32 * Ed; idx += 256)
            w_s[idx] = Wih[(size_t)rbase * Ed + idx];
        __syncthreads();

        float acc[4];
#pragma unroll
        for (int i = 0; i < 4; i++) acc[i] = bias[rbase + wr * 4 + i];

#pragma unroll 4
        for (int k = 0; k < Ed; k++) {
            float xv = x_s[k * Bd + lane];
#pragma unroll
            for (int i = 0; i < 4; i++)
                acc[i] = fmaf(w_s[(wr * 4 + i) * Ed + k], xv, acc[i]);
        }

        float* o = xproj + ((size_t)t * G4 + rbase + wr * 4) * Bd + lane;
#pragma unroll
        for (int i = 0; i < 4; i++) o[(size_t)i * Bd] = acc[i];
    }
}

// ---------------- persistent recurrence kernel (R12/R14-proven: v3 + fused A-split) ----------------
__global__ void __launch_bounds__(NTHR, 1) recur_kernel(
    const float* __restrict__ Whh_e,
    const float* __restrict__ Whh_d,
    float* __restrict__ out)
{
    __shared__ float  w_s[8 * Hd];        // [r][k] 8KB
    __shared__ float2 part[8][8][16];     // [warp][r][bp] 8KB
    __shared__ float2 g_sm[8][16];        // reduced gates [r][bp]
    __shared__ float2 c_sm[32];           // c state

    const int tid  = threadIdx.x;
    const int u0   = blockIdx.x * 2;
    const int lane = tid & 31;
    const int w    = tid >> 5;
    const int bp   = lane & 15;
    const int ksub = lane >> 4;
    const int kb   = w * 32 + ksub * 16;  // this thread's k base (16 ks)

    for (int i = tid; i < 8 * Hd; i += NTHR) {
        int r = i >> 8, k = i & 255;
        w_s[i] = Whh_e[(size_t)((r & 3) * Hd + u0 + (r >> 2)) * Hd + k];
    }
    if (tid < 32) c_sm[tid] = make_float2(0.f, 0.f);
    __syncthreads();

    const int rr = tid >> 4, bq = tid & 15;
    const int growr = (rr & 3) * Hd + u0 + (rr >> 2);

    float2 xcur = make_float2(0.f, 0.f);
    if (tid < 128)
        xcur = *(const float2*)(g_xe + (size_t)growr * Bd + bq * 2);

    for (int step = 0; step < NSTEPS; step++) {
        const bool dec = (step >= Sd);
        const int  t   = dec ? step - Sd : step;

        if (step == Sd) {
            for (int i = tid; i < 8 * Hd; i += NTHR) {
                int r = i >> 8, k = i & 255;
                w_s[i] = Whh_d[(size_t)((r & 3) * Hd + u0 + (r >> 2)) * Hd + k];
            }
            __syncthreads();
        }

        const float2* hp = (const float2*)((step & 1) ? g_h0 : g_h1);

        float2 hv[16];
#pragma unroll
        for (int j = 0; j < 16; j++)
            hv[j] = hp[(kb + j) * 16 + bp];

        float2 acc[8];
#pragma unroll
        for (int r = 0; r < 8; r++) acc[r] = make_float2(0.f, 0.f);
#pragma unroll
        for (int j = 0; j < 16; j += 4) {
#pragma unroll
            for (int r = 0; r < 8; r++) {
                float4 wv = *(const float4*)(w_s + r * Hd + kb + j);
                acc[r] = ffma2(make_float2(wv.x, wv.x), hv[j + 0], acc[r]);
                acc[r] = ffma2(make_float2(wv.y, wv.y), hv[j + 1], acc[r]);
                acc[r] = ffma2(make_float2(wv.z, wv.z), hv[j + 2], acc[r]);
                acc[r] = ffma2(make_float2(wv.w, wv.w), hv[j + 3], acc[r]);
            }
        }
#pragma unroll
        for (int r = 0; r < 8; r++) {
            acc[r].x += __shfl_xor_sync(0xffffffff, acc[r].x, 16);
            acc[r].y += __shfl_xor_sync(0xffffffff, acc[r].y, 16);
        }
        if (ksub == 0) {
#pragma unroll
            for (int r = 0; r < 8; r++) part[w][r][bp] = acc[r];
        }
        __syncthreads();

        if (tid < 128) {
            float2 s = xcur;
#pragma unroll
            for (int ww = 0; ww < 8; ww++) {
                float2 p = part[ww][rr][bq];
                s.x += p.x; s.y += p.y;
            }
            g_sm[rr][bq] = s;
            if (step + 1 < NSTEPS) {
                const bool decn = (step + 1 >= Sd);
                const int  tn   = decn ? step + 1 - Sd : step + 1;
                const float* xp = decn ? g_xd : g_xe;
                xcur = *(const float2*)(xp + ((size_t)tn * G4 + growr) * Bd + bq * 2);
            }
        }
        __syncthreads();

        float* hw = (step & 1) ? g_h1 : g_h0;
        if (tid < 32) {
            int iu2 = tid >> 4, bp2 = tid & 15;
            float2 gi = g_sm[iu2 * 4 + 0][bp2];
            float2 gf = g_sm[iu2 * 4 + 1][bp2];
            float2 gg = g_sm[iu2 * 4 + 2][bp2];
            float2 go = g_sm[iu2 * 4 + 3][bp2];
            float2 c = c_sm[tid];
            c.x = sigm(gf.x) * c.x + sigm(gi.x) * tanhf(gg.x);
            c.y = sigm(gf.y) * c.y + sigm(gi.y) * tanhf(gg.y);
            float2 h;
            h.x = sigm(go.x) * tanhf(c.x);
            h.y = sigm(go.y) * tanhf(c.y);
            c_sm[tid] = c;
            int u = u0 + iu2;
            *(float2*)(hw + u * Bd + bp2 * 2) = h;
            if (dec) {
                int m0 = t * Bd + bp2 * 2;
                __nv_bfloat16 xh = __float2bfloat16(h.x);
                __nv_bfloat16 xl = __float2bfloat16(h.x - __bfloat162float(xh));
                __nv_bfloat16 yh = __float2bfloat16(h.y);
                __nv_bfloat16 yl = __float2bfloat16(h.y - __bfloat162float(yh));
                g_Ahi[(size_t)m0 * Hd + u]       = xh;
                g_Alo[(size_t)m0 * Hd + u]       = xl;
                g_Ahi[(size_t)(m0 + 1) * Hd + u] = yh;
                g_Alo[(size_t)(m0 + 1) * Hd + u] = yl;
            }
            if (step == NSTEPS - 1) {
                size_t base = (size_t)Bd * Td * Vd;
                int b0 = bp2 * 2;
                out[base + (size_t)b0 * Hd + u]       = h.x;
                out[base + (size_t)(b0 + 1) * Hd + u] = h.y;
                out[base + (size_t)Bd * Hd + (size_t)b0 * Hd + u]       = c.x;
                out[base + (size_t)Bd * Hd + (size_t)(b0 + 1) * Hd + u] = c.y;
            }
        }
        __syncthreads();   // h stores complete block-wide

        // grid barrier (monotonic atomic counter — R14-proven)
        if (step < NSTEPS - 1) {
            if (tid == 0) {
                __threadfence();
                atomicAdd(&g_bar, 1u);
                unsigned target = (unsigned)(NBLK * (step + 1));
                while (ld_acquire_gpu(&g_bar) < target) { }
            }
            __syncthreads();
        }
    }
}

// ---------------- bf16 split conversion for W ----------------
__global__ void convW_kernel(const float* __restrict__ W) {
    int i = blockIdx.x * blockDim.x + threadIdx.x;   // group of 4 floats
    const int total = Vd * Hd / 4;
    if (i >= total) return;
    float4 v = ((const float4*)W)[i];
    __nv_bfloat162 h01, h23, l01, l23;
    h01.x = __float2bfloat16(v.x); l01.x = __float2bfloat16(v.x - __bfloat162float(h01.x));
    h01.y = __float2bfloat16(v.y); l01.y = __float2bfloat16(v.y - __bfloat162float(h01.y));
    h23.x = __float2bfloat16(v.z); l23.x = __float2bfloat16(v.z - __bfloat162float(h23.x));
    h23.y = __float2bfloat16(v.w); l23.y = __float2bfloat16(v.w - __bfloat162float(h23.y));
    ((__nv_bfloat162*)g_Whi)[i * 2]     = h01;
    ((__nv_bfloat162*)g_Whi)[i * 2 + 1] = h23;
    ((__nv_bfloat162*)g_Wlo)[i * 2]     = l01;
    ((__nv_bfloat162*)g_Wlo)[i * 2 + 1] = l23;
}

// ---------------- FC via mma.sync (bf16 split, HMMA, cp.async double-buffer) ----------------
#define BKC   32
#define NCH   (Hd / BKC)      // 8
#define LDA   40              // smem row stride (bf16) — conflict-free for ldmatrix
#define TILE_BYTES (128 * LDA * 2)   // 10240 per tile
#define STG_SZ (4 * TILE_BYTES)      // 40960 per stage (AH, AL, BH, BL)
#define SM_BIAS (2 * STG_SZ)         // 81920
#define SM_TOTAL (SM_BIAS + 512)     // 82432

__device__ __forceinline__ void cp16(uint32_t dst, const void* src) {
    asm volatile("cp.async.cg.shared.global [%0], [%1], 16;" :: "r"(dst), "l"(src));
}
#define CP_COMMIT() asm volatile("cp.async.commit_group;" ::: "memory")

__device__ __forceinline__ void ldsm_x4(uint32_t* r, uint32_t addr) {
    asm volatile("ldmatrix.sync.aligned.m8n8.x4.shared.b16 {%0,%1,%2,%3}, [%4];"
                 : "=r"(r[0]), "=r"(r[1]), "=r"(r[2]), "=r"(r[3]) : "r"(addr));
}
__device__ __forceinline__ void ldsm_x2(uint32_t* r, uint32_t addr) {
    asm volatile("ldmatrix.sync.aligned.m8n8.x2.shared.b16 {%0,%1}, [%2];"
                 : "=r"(r[0]), "=r"(r[1]) : "r"(addr));
}
__device__ __forceinline__ void mma16816(float* c, const uint32_t* a, const uint32_t* b) {
    asm volatile("mma.sync.aligned.m16n8k16.row.col.f32.bf16.bf16.f32 "
                 "{%0,%1,%2,%3}, {%4,%5,%6,%7}, {%8,%9}, {%0,%1,%2,%3};"
                 : "+f"(c[0]), "+f"(c[1]), "+f"(c[2]), "+f"(c[3])
                 : "r"(a[0]), "r"(a[1]), "r"(a[2]), "r"(a[3]), "r"(b[0]), "r"(b[1]));
}

__global__ void __launch_bounds__(256) fcmma_kernel(const float* __restrict__ bias,
                                                    float* __restrict__ out)
{
    extern __shared__ __align__(16) char dsm[];

    const int tid = threadIdx.x;
    const int lane = tid & 31;
    const int wid = tid >> 5;
    const int vbase = blockIdx.x * 128;
    const int mbase = blockIdx.y * 128;
    const int warp_m = (wid & 1) * 64;
    const int warp_n = (wid >> 1) * 32;

    float* bias_s = (float*)(dsm + SM_BIAS);
    if (tid < 32) ((float4*)bias_s)[tid] = ((const float4*)(bias + vbase))[tid];

    const uint32_t sb = smem_u32(dsm);

    // copy-thread mapping: idx in [0,512) covers 128 rows x 4 16B-chunks
    const int cr0 = tid >> 2,          cj0 = (tid & 3);
    const int cr1 = (tid + 256) >> 2,  cj1 = ((tid + 256) & 3);

    auto issue = [&](int ch, int stg) {
        const int kk = ch * BKC;
        const uint32_t base = sb + stg * STG_SZ;
        {
            uint32_t d = base + (uint32_t)(cr0 * LDA + cj0 * 8) * 2;
            const size_t ga = (size_t)(mbase + cr0) * Hd + kk + cj0 * 8;
            const size_t gb = (size_t)(vbase + cr0) * Hd + kk + cj0 * 8;
            cp16(d,                  g_Ahi + ga);
            cp16(d + TILE_BYTES,     g_Alo + ga);
            cp16(d + 2 * TILE_BYTES, g_Whi + gb);
            cp16(d + 3 * TILE_BYTES, g_Wlo + gb);
        }
        {
            uint32_t d = base + (uint32_t)(cr1 * LDA + cj1 * 8) * 2;
            const size_t ga = (size_t)(mbase + cr1) * Hd + kk + cj1 * 8;
            const size_t gb = (size_t)(vbase + cr1) * Hd + kk + cj1 * 8;
            cp16(d,                  g_Ahi + ga);
            cp16(d + TILE_BYTES,     g_Alo + ga);
            cp16(d + 2 * TILE_BYTES, g_Whi + gb);
            cp16(d + 3 * TILE_BYTES, g_Wlo + gb);
        }
    };

    const int arow = warp_m + (lane & 15);
    const int acol = (lane >> 4) << 3;
    const int l16  = lane & 15;
    const int brow = warp_n + (l16 & 7);
    const int bcol = ((l16 >> 3) & 1) << 3;

    float acc[4][4][4];
#pragma unroll
    for (int i = 0; i < 4; i++)
#pragma unroll
        for (int j = 0; j < 4; j++)
#pragma unroll
            for (int r = 0; r < 4; r++) acc[i][j][r] = 0.0f;

    issue(0, 0);
    CP_COMMIT();

    for (int ch = 0; ch < NCH; ch++) {
        if (ch + 1 < NCH) {
            issue(ch + 1, (ch + 1) & 1);
            CP_COMMIT();
            asm volatile("cp.async.wait_group 1;" ::: "memory");
        } else {
            asm volatile("cp.async.wait_group 0;" ::: "memory");
        }
        __syncthreads();

        const uint32_t stg = sb + (ch & 1) * STG_SZ;
        const uint32_t uAh = stg;
        const uint32_t uAl = stg + TILE_BYTES;
        const uint32_t uBh = stg + 2 * TILE_BYTES;
        const uint32_t uBl = stg + 3 * TILE_BYTES;

#pragma unroll
        for (int k16 = 0; k16 < BKC; k16 += 16) {
            uint32_t bh[4][2], bl[4][2];
#pragma unroll
            for (int ni = 0; ni < 4; ni++) {
                uint32_t boff = (uint32_t)(((brow + ni * 8) * LDA + k16 + bcol) * 2);
                ldsm_x2(bh[ni], uBh + boff);
                ldsm_x2(bl[ni], uBl + boff);
            }
#pragma unroll
            for (int mi = 0; mi < 4; mi++) {
                uint32_t aoff = (uint32_t)(((arow + mi * 16) * LDA + k16 + acol) * 2);
                uint32_t ah[4], al[4];
                ldsm_x4(ah, uAh + aoff);
                ldsm_x4(al, uAl + aoff);
#pragma unroll
                for (int ni = 0; ni < 4; ni++) {
                    mma16816(acc[mi][ni], ah, bh[ni]);
                    mma16816(acc[mi][ni], ah, bl[ni]);
                    mma16816(acc[mi][ni], al, bh[ni]);
                }
            }
        }
        __syncthreads();
    }

    // epilogue: direct gmem writes with bias
#pragma unroll
    for (int mi = 0; mi < 4; mi++) {
        int gm0 = mbase + warp_m + mi * 16 + (lane >> 2);
#pragma unroll
        for (int ni = 0; ni < 4; ni++) {
            int cloc = warp_n + ni * 8 + ((lane & 3) << 1);
            int gv = vbase + cloc;
            float b0 = bias_s[cloc], b1 = bias_s[cloc + 1];
#pragma unroll
            for (int half = 0; half < 2; half++) {
                int gm = gm0 + half * 8;
                if (gm < FMROWS) {
                    int b = gm & 31, t = gm >> 5;
                    float2 r;
                    r.x = acc[mi][ni][half * 2 + 0] + b0;
                    r.y = acc[mi][ni][half * 2 + 1] + b1;
                    *(float2*)(out + ((size_t)b * Td + t + 1) * Vd + gv) = r;
                }
            }
        }
    }
}

// ---------------- launch (fork-join stream overlap, graph-capturable) ----------------
extern "C" void kernel_launch(void* const* d_in, const int* in_sizes, int n_in,
                              void* d_out, int out_size)
{
    const int*   src     = (const int*)  d_in[0];
    const int*   trg     = (const int*)  d_in[1];
    const float* emb_src = (const float*)d_in[2];
    const float* Wih_e   = (const float*)d_in[3];
    const float* Whh_e   = (const float*)d_in[4];
    const float* b_e     = (const float*)d_in[5];
    const float* emb_trg = (const float*)d_in[6];
    const float* Wih_d   = (const float*)d_in[7];
    const float* Whh_d   = (const float*)d_in[8];
    const float* b_d     = (const float*)d_in[9];
    const float* Wfc     = (const float*)d_in[10];
    const float* bfc     = (const float*)d_in[11];
    float* out = (float*)d_out;

    // Static side streams/events (created once, outside any capture)
    static cudaStream_t sB = nullptr, sC = nullptr;
    static cudaEvent_t eRoot = nullptr, eB = nullptr, eC = nullptr;
    if (sB == nullptr) {
        cudaStreamCreateWithFlags(&sB, cudaStreamNonBlocking);
        cudaStreamCreateWithFlags(&sC, cudaStreamNonBlocking);
        cudaEventCreateWithFlags(&eRoot, cudaEventDisableTiming);
        cudaEventCreateWithFlags(&eB, cudaEventDisableTiming);
        cudaEventCreateWithFlags(&eC, cudaEventDisableTiming);
        cudaFuncSetAttribute(fcmma_kernel,
                             cudaFuncAttributeMaxDynamicSharedMemorySize, SM_TOTAL);
    }

    // fork from the (captured) default stream
    cudaEventRecord(eRoot, 0);
    cudaStreamWaitEvent(sB, eRoot, 0);
    cudaStreamWaitEvent(sC, eRoot, 0);

    // branch B: init + decoder projection (needed by recur)
    init_kernel<<<512, 256, 0, sB>>>(out);
    proj_kernel<<<dim3(4, Td - 1), 256, 0, sB>>>(trg, Td, emb_trg, Wih_d, b_d, 1);
    cudaEventRecord(eB, sB);

    // branch C: FC weight split (needed only by fcmma)
    convW_kernel<<<(Vd * Hd / 4 + 255) / 256, 256, 0, sC>>>(Wfc);
    cudaEventRecord(eC, sC);

    // main stream: encoder projection, then recurrence, then FC
    proj_kernel<<<dim3(4, Sd), 256>>>(src, Sd, emb_src, Wih_e, b_e, 0);

    cudaStreamWaitEvent(0, eB, 0);   // init + proj_dec done
    recur_kernel<<<NBLK, NTHR>>>(Whh_e, Whh_d, out);

    cudaStreamWaitEvent(0, eC, 0);   // convW done
    fcmma_kernel<<<dim3(Vd / 128, MPAD / 128), 256, SM_TOTAL>>>(bfc, out);
}